// round 7
// baseline (speedup 1.0000x reference)
#include <cuda_runtime.h>
#include <math.h>
#include <stdint.h>

typedef unsigned long long ull;

#define SEQ   1024
#define BATCH 64
#define DH    256
#define DIN   256
#define NBLK  128
#define NTHR  256

// ---------------- device scratch (static allocs only) -----------------------
__device__ float    g_xq[(size_t)SEQ * 1024 * 64];   // [t][gatecol][b], 256MB
__device__ float    g_hbuf[2][DH * BATCH];           // double-buffered h, [unit][batch]
__device__ unsigned g_pflag[SEQ + 1][NBLK];          // per-step, per-producer flags

// ---------------- f32x2 packed helpers (Blackwell) --------------------------
__device__ __forceinline__ ull fma2(ull a, ull b, ull c) {
    ull d;
    asm("fma.rn.f32x2 %0, %1, %2, %3;" : "=l"(d) : "l"(a), "l"(b), "l"(c));
    return d;
}
__device__ __forceinline__ ull add2(ull a, ull b) {
    ull d;
    asm("add.rn.f32x2 %0, %1, %2;" : "=l"(d) : "l"(a), "l"(b));
    return d;
}
__device__ __forceinline__ ull pack2(float x, float y) {
    ull r;
    asm("mov.b64 %0, {%1, %2};" : "=l"(r) : "f"(x), "f"(y));
    return r;
}
__device__ __forceinline__ float2 unpack2(ull v) {
    float2 r;
    asm("mov.b64 {%0, %1}, %2;" : "=f"(r.x), "=f"(r.y) : "l"(v));
    return r;
}
__device__ __forceinline__ ull ldcg_u64(const void* p) {
    ull v;
    asm volatile("ld.global.cg.u64 %0, [%1];" : "=l"(v) : "l"(p));
    return v;
}
__device__ __forceinline__ unsigned ld_acq(const unsigned* p) {
    unsigned v;
    asm volatile("ld.acquire.gpu.global.u32 %0, [%1];" : "=r"(v) : "l"(p));
    return v;
}
__device__ __forceinline__ void st_rel(unsigned* p, unsigned v) {
    asm volatile("st.release.gpu.global.u32 [%0], %1;" :: "l"(p), "r"(v) : "memory");
}
// fast tanh: 1 - 2/(exp(2x)+1); exp(inf)->inf -> 1; exp(-inf)->0 -> -1. err ~1e-6.
__device__ __forceinline__ float ftanh(float x) {
    float e = __expf(2.0f * x);
    return 1.0f - 2.0f / (e + 1.0f);
}
__device__ __forceinline__ float fsigmoid(float x) {
    return 1.0f / (1.0f + __expf(-x));
}

// ======================= Phase 1: X projection GEMM =========================
// g_xq[t, c, b] = sum_k X[t,b,k] * W_g[k, j] + bias_g[j],  c = g*256 + j
__global__ __launch_bounds__(256) void xproj_kernel(
    const float* __restrict__ X,
    const float* __restrict__ Wf, const float* __restrict__ Wi,
    const float* __restrict__ Wg, const float* __restrict__ Wo,
    const float* __restrict__ bf, const float* __restrict__ bi,
    const float* __restrict__ bg, const float* __restrict__ bo)
{
    __shared__ float As[16 * 68];   // [k][row]
    __shared__ float Bs[16 * 68];   // [k][col]

    const int t    = blockIdx.y;
    const int bx   = blockIdx.x;           // 0..15
    const int gsel = bx >> 2;
    const int j0   = (bx & 3) * 64;
    const float* W    = (gsel == 0) ? Wf : (gsel == 1) ? Wi : (gsel == 2) ? Wg : Wo;
    const float* bias = (gsel == 0) ? bf : (gsel == 1) ? bi : (gsel == 2) ? bg : bo;

    const int tx = threadIdx.x;

    // re-zero flags every replay (xproj completes before lstm launches)
    if (bx == 0 && tx < 128) {
        g_pflag[t][tx] = 0u;
        if (t == 0) g_pflag[SEQ][tx] = 0u;
    }

    const int trow4 = (tx >> 4) * 4;
    const int tcol4 = (tx & 15) * 4;

    const int arow = tx >> 2;
    const int akq  = (tx & 3) * 4;
    const int bk   = tx >> 4;
    const int bc4  = (tx & 15) * 4;

    const float* Aptr = X + ((size_t)t * 64 + arow) * 256 + akq;
    const float* Bptr = W + (size_t)bk * 256 + j0 + bc4;

    ull acc[8];
    #pragma unroll
    for (int i = 0; i < 8; ++i) acc[i] = 0ull;

    float4 aReg = *(const float4*)Aptr;
    float4 bReg = *(const float4*)Bptr;

    for (int kt = 0; kt < 16; ++kt) {
        __syncthreads();
        As[(akq + 0) * 68 + arow] = aReg.x;
        As[(akq + 1) * 68 + arow] = aReg.y;
        As[(akq + 2) * 68 + arow] = aReg.z;
        As[(akq + 3) * 68 + arow] = aReg.w;
        *(float4*)&Bs[bk * 68 + bc4] = bReg;
        if (kt < 15) {
            aReg = *(const float4*)(Aptr + (kt + 1) * 16);
            bReg = *(const float4*)(Bptr + (size_t)(kt + 1) * 16 * 256);
        }
        __syncthreads();

        #pragma unroll
        for (int k = 0; k < 16; ++k) {
            float4 a4 = *(const float4*)&As[k * 68 + trow4];
            float4 b4 = *(const float4*)&Bs[k * 68 + tcol4];
            ull a01 = pack2(a4.x, a4.y);
            ull a23 = pack2(a4.z, a4.w);
            ull bb;
            bb = pack2(b4.x, b4.x); acc[0] = fma2(a01, bb, acc[0]); acc[1] = fma2(a23, bb, acc[1]);
            bb = pack2(b4.y, b4.y); acc[2] = fma2(a01, bb, acc[2]); acc[3] = fma2(a23, bb, acc[3]);
            bb = pack2(b4.z, b4.z); acc[4] = fma2(a01, bb, acc[4]); acc[5] = fma2(a23, bb, acc[5]);
            bb = pack2(b4.w, b4.w); acc[6] = fma2(a01, bb, acc[6]); acc[7] = fma2(a23, bb, acc[7]);
        }
    }

    #pragma unroll
    for (int jj = 0; jj < 4; ++jj) {
        float bv = bias[j0 + tcol4 + jj];
        float2 p01 = unpack2(acc[2 * jj]);
        float2 p23 = unpack2(acc[2 * jj + 1]);
        float4 outv = make_float4(p01.x + bv, p01.y + bv, p23.x + bv, p23.y + bv);
        size_t c = (size_t)bx * 64 + tcol4 + jj;
        *(float4*)&g_xq[(size_t)t * 65536 + c * 64 + trow4] = outv;
    }
}

// ======================= Phase 2: persistent recurrence =====================
// 128 CTAs x 256 thr. CTA owns 2 hidden units (8 gate-cols c = g*2+uu).
// Warp = one k-chunk of 32 k; lane = batch-pair. Per k: 1 LDG.cg.64 h-pair +
// 4 broadcast LDS.128 w-dup + 8 FFMA2. 8-deep smem partial reduce. Producer
// signaling via per-CTA release-store flags (no atomic contention).
__global__ __launch_bounds__(NTHR, 1) void lstm_seq_kernel(
    const float* __restrict__ Wf, const float* __restrict__ Wi,
    const float* __restrict__ Wg, const float* __restrict__ Wo,
    float* __restrict__ out)
{
    __shared__ ull wh2[2048];      // [k][8c] dup pairs, 16KB
    __shared__ ull pp[2048];       // [8 kc][8 c][32 bp] partials, 16KB
    __shared__ ull gate_s[256];    // [8 c][32 bp]
    __shared__ ull c_s[64];        // [2 u][32 bp]

    const int tx   = threadIdx.x;
    const int bx   = blockIdx.x;
    const int u0   = bx << 1;
    const int kc   = tx >> 5;      // warp id = k-chunk (32 k each)
    const int lane = tx & 31;      // batch-pair

    // ---- load Wh slice (rows 256..511), duplicated pairs wh2[k*8 + c] ----
    for (int idx = tx; idx < 2048; idx += NTHR) {
        int k = idx >> 3, c = idx & 7;
        const float* W = (c < 4) ? ((c < 2) ? Wf : Wi) : ((c < 6) ? Wg : Wo);
        float w = W[(size_t)(256 + k) * 256 + u0 + (c & 1)];
        wh2[idx] = pack2(w, w);
    }

    // ---- init h(0)=0, c=0, signal flag[0] ----
    if (tx < 64) {
        c_s[tx] = 0ull;
        int u = tx >> 5, bp = tx & 31;
        *(ull*)&g_hbuf[0][(u0 + u) * 64 + (bp << 1)] = 0ull;
    }
    __syncthreads();
    if (tx == 0) st_rel(&g_pflag[0][bx], 1u);

    // reduce-role constants: col rc = tx>>5 (reuse kc), bp rbp = lane
    const int rg = kc >> 1;        // gate of my reduce column
    const size_t xq_off = (size_t)(rg * 256 + u0 + (kc & 1)) * 64 + (lane << 1);

    float* outs = out;
    float* hxo  = out + (size_t)SEQ * 64 * 256;
    float* cxo  = hxo + 64 * 256;

    const ull* wbase = wh2 + (kc << 8);    // wh2[(kc*32 + k)*8]

    for (int t = 0; t < SEQ; ++t) {
        // prefetch x-projection (ready since xproj kernel)
        ull xq = *(const ull*)&g_xq[(size_t)t * 65536 + xq_off];

        // wait for all 128 producers of h(t): warp 7 lanes poll 4 flags each
        if (tx >= 224) {
            const unsigned* fp = &g_pflag[t][(tx - 224) << 2];
            for (;;) {
                unsigned a = ld_acq(fp), b = ld_acq(fp + 1);
                unsigned c = ld_acq(fp + 2), d = ld_acq(fp + 3);
                if (a & b & c & d) break;
            }
        }
        __syncthreads();

        // ---- GEMM: acc[c] += sum over 32 k of h[k][2lane..] * w[k][c] ----
        const float* hb = g_hbuf[t & 1] + (kc << 11) + (lane << 1);  // (kc*32)*64
        ull acc[8];
        #pragma unroll
        for (int i = 0; i < 8; ++i) acc[i] = 0ull;
        #pragma unroll 8
        for (int k = 0; k < 32; ++k) {
            ull hh = ldcg_u64(hb + (k << 6));
            const ulonglong2* wv = (const ulonglong2*)(wbase + (k << 3));
            ulonglong2 w01 = wv[0], w23 = wv[1], w45 = wv[2], w67 = wv[3];
            acc[0] = fma2(hh, w01.x, acc[0]); acc[1] = fma2(hh, w01.y, acc[1]);
            acc[2] = fma2(hh, w23.x, acc[2]); acc[3] = fma2(hh, w23.y, acc[3]);
            acc[4] = fma2(hh, w45.x, acc[4]); acc[5] = fma2(hh, w45.y, acc[5]);
            acc[6] = fma2(hh, w67.x, acc[6]); acc[7] = fma2(hh, w67.y, acc[7]);
        }
        // store partials: pp[kc][c][lane]
        {
            ull* pdst = pp + (kc << 8) + lane;
            #pragma unroll
            for (int c = 0; c < 8; ++c) pdst[c << 5] = acc[c];
        }
        __syncthreads();

        // ---- reduce 8 partials + xq, activation ----
        ull a0 = add2(pp[tx],        pp[tx + 256]);
        ull a1 = add2(pp[tx + 512],  pp[tx + 768]);
        ull a2 = add2(pp[tx + 1024], pp[tx + 1280]);
        ull a3 = add2(pp[tx + 1536], pp[tx + 1792]);
        ull s  = add2(add2(add2(a0, a1), add2(a2, a3)), xq);

        float2 v = unpack2(s);
        float2 a;
        if (rg == 2) { a.x = ftanh(v.x);    a.y = ftanh(v.y); }
        else         { a.x = fsigmoid(v.x); a.y = fsigmoid(v.y); }
        gate_s[tx] = pack2(a.x, a.y);
        __syncthreads();

        // ---- state update by warps 0-1 only; others run ahead to poll ----
        if (tx < 64) {
            int u = tx >> 5, bp = tx & 31;
            float2 f  = unpack2(gate_s[tx]);
            float2 ii = unpack2(gate_s[64 + tx]);
            float2 gg = unpack2(gate_s[128 + tx]);
            float2 oo = unpack2(gate_s[192 + tx]);
            float2 co = unpack2(c_s[tx]);
            float c0 = f.x * co.x + ii.x * gg.x;
            float c1 = f.y * co.y + ii.y * gg.y;
            c_s[tx] = pack2(c0, c1);
            float h0 = oo.x * ftanh(c0);
            float h1 = oo.y * ftanh(c1);
            int j = u0 + u;
            int b = bp << 1;
            *(ull*)&g_hbuf[(t + 1) & 1][j * 64 + b] = pack2(h0, h1);
            outs[((size_t)t * 64 + b) * 256 + j]     = h0;
            outs[((size_t)t * 64 + b + 1) * 256 + j] = h1;
            if (t == SEQ - 1) {
                hxo[b * 256 + j] = h0; hxo[(b + 1) * 256 + j] = h1;
                cxo[b * 256 + j] = c0; cxo[(b + 1) * 256 + j] = c1;
            }
            asm volatile("bar.sync 1, 64;" ::: "memory");   // warps 0-1 only
            if (tx == 0) st_rel(&g_pflag[t + 1][bx], 1u);
        }
        // no full sync here: next-iter __syncthreads after the poll covers
        // gate_s/pp reuse, and the poller waits on our own flag anyway.
    }
}

// ============================== launch ======================================
extern "C" void kernel_launch(void* const* d_in, const int* in_sizes, int n_in,
                              void* d_out, int out_size)
{
    (void)in_sizes; (void)n_in; (void)out_size;
    const float* X  = (const float*)d_in[0];
    const float* Wf = (const float*)d_in[1];
    const float* bf = (const float*)d_in[2];
    const float* Wi = (const float*)d_in[3];
    const float* bi = (const float*)d_in[4];
    const float* Wg = (const float*)d_in[5];
    const float* bg = (const float*)d_in[6];
    const float* Wo = (const float*)d_in[7];
    const float* bo = (const float*)d_in[8];
    float* out = (float*)d_out;

    dim3 g1(16, 1024);
    xproj_kernel<<<g1, 256>>>(X, Wf, Wi, Wg, Wo, bf, bi, bg, bo);

    lstm_seq_kernel<<<NBLK, NTHR>>>(Wf, Wi, Wg, Wo, out);
}

// round 10
// speedup vs baseline: 2.1399x; 2.1399x over previous
#include <cuda_runtime.h>
#include <math.h>
#include <stdint.h>

typedef unsigned long long ull;

#define SEQ   1024
#define BATCH 64
#define DH    256
#define DIN   256
#define NBLK  128
#define NTHR  256

// ---------------- device scratch (static allocs only) -----------------------
__device__ float    g_xq[(size_t)SEQ * 1024 * 64];   // [t][gatecol][b], 256MB
__device__ float    g_hbuf[2][DH * BATCH];           // double-buffered h, [unit][batch]
// counting flags: one per (step, producer-group of 16 CTAs), padded 128B apart
__device__ unsigned g_cflag[(SEQ + 1) * 8 * 32];

// ---------------- f32x2 packed helpers (Blackwell) --------------------------
__device__ __forceinline__ ull fma2(ull a, ull b, ull c) {
    ull d;
    asm("fma.rn.f32x2 %0, %1, %2, %3;" : "=l"(d) : "l"(a), "l"(b), "l"(c));
    return d;
}
__device__ __forceinline__ ull add2(ull a, ull b) {
    ull d;
    asm("add.rn.f32x2 %0, %1, %2;" : "=l"(d) : "l"(a), "l"(b));
    return d;
}
__device__ __forceinline__ ull pack2(float x, float y) {
    ull r;
    asm("mov.b64 %0, {%1, %2};" : "=l"(r) : "f"(x), "f"(y));
    return r;
}
__device__ __forceinline__ float2 unpack2(ull v) {
    float2 r;
    asm("mov.b64 {%0, %1}, %2;" : "=f"(r.x), "=f"(r.y) : "l"(v));
    return r;
}
__device__ __forceinline__ ull ldcg_u64(const void* p) {
    ull v;
    asm volatile("ld.global.cg.u64 %0, [%1];" : "=l"(v) : "l"(p));
    return v;
}
__device__ __forceinline__ unsigned ld_acq(const unsigned* p) {
    unsigned v;
    asm volatile("ld.acquire.gpu.global.u32 %0, [%1];" : "=r"(v) : "l"(p));
    return v;
}
__device__ __forceinline__ void red_rel(unsigned* p) {
    unsigned one = 1u;
    asm volatile("red.release.gpu.global.add.u32 [%0], %1;" :: "l"(p), "r"(one) : "memory");
}
// fast tanh: 1 - 2/(exp(2x)+1)
__device__ __forceinline__ float ftanh(float x) {
    float e = __expf(2.0f * x);
    return 1.0f - 2.0f / (e + 1.0f);
}
__device__ __forceinline__ float fsigmoid(float x) {
    return 1.0f / (1.0f + __expf(-x));
}

// ======================= Phase 1: X projection GEMM =========================
__global__ __launch_bounds__(256) void xproj_kernel(
    const float* __restrict__ X,
    const float* __restrict__ Wf, const float* __restrict__ Wi,
    const float* __restrict__ Wg, const float* __restrict__ Wo,
    const float* __restrict__ bf, const float* __restrict__ bi,
    const float* __restrict__ bg, const float* __restrict__ bo)
{
    __shared__ float As[16 * 68];   // [k][row]
    __shared__ float Bs[16 * 68];   // [k][col]

    const int t    = blockIdx.y;
    const int bx   = blockIdx.x;           // 0..15
    const int gsel = bx >> 2;
    const int j0   = (bx & 3) * 64;
    const float* W    = (gsel == 0) ? Wf : (gsel == 1) ? Wi : (gsel == 2) ? Wg : Wo;
    const float* bias = (gsel == 0) ? bf : (gsel == 1) ? bi : (gsel == 2) ? bg : bo;

    const int tx = threadIdx.x;

    // re-zero counting flags every replay (xproj completes before lstm starts)
    if (bx == 0) {
        if (tx < 8) g_cflag[((t << 3) + tx) << 5] = 0u;
        if (t == 0 && tx >= 8 && tx < 16) g_cflag[((SEQ << 3) + (tx - 8)) << 5] = 0u;
    }

    const int trow4 = (tx >> 4) * 4;
    const int tcol4 = (tx & 15) * 4;

    const int arow = tx >> 2;
    const int akq  = (tx & 3) * 4;
    const int bk   = tx >> 4;
    const int bc4  = (tx & 15) * 4;

    const float* Aptr = X + ((size_t)t * 64 + arow) * 256 + akq;
    const float* Bptr = W + (size_t)bk * 256 + j0 + bc4;

    ull acc[8];
    #pragma unroll
    for (int i = 0; i < 8; ++i) acc[i] = 0ull;

    float4 aReg = *(const float4*)Aptr;
    float4 bReg = *(const float4*)Bptr;

    for (int kt = 0; kt < 16; ++kt) {
        __syncthreads();
        As[(akq + 0) * 68 + arow] = aReg.x;
        As[(akq + 1) * 68 + arow] = aReg.y;
        As[(akq + 2) * 68 + arow] = aReg.z;
        As[(akq + 3) * 68 + arow] = aReg.w;
        *(float4*)&Bs[bk * 68 + bc4] = bReg;
        if (kt < 15) {
            aReg = *(const float4*)(Aptr + (kt + 1) * 16);
            bReg = *(const float4*)(Bptr + (size_t)(kt + 1) * 16 * 256);
        }
        __syncthreads();

        #pragma unroll
        for (int k = 0; k < 16; ++k) {
            float4 a4 = *(const float4*)&As[k * 68 + trow4];
            float4 b4 = *(const float4*)&Bs[k * 68 + tcol4];
            ull a01 = pack2(a4.x, a4.y);
            ull a23 = pack2(a4.z, a4.w);
            ull bb;
            bb = pack2(b4.x, b4.x); acc[0] = fma2(a01, bb, acc[0]); acc[1] = fma2(a23, bb, acc[1]);
            bb = pack2(b4.y, b4.y); acc[2] = fma2(a01, bb, acc[2]); acc[3] = fma2(a23, bb, acc[3]);
            bb = pack2(b4.z, b4.z); acc[4] = fma2(a01, bb, acc[4]); acc[5] = fma2(a23, bb, acc[5]);
            bb = pack2(b4.w, b4.w); acc[6] = fma2(a01, bb, acc[6]); acc[7] = fma2(a23, bb, acc[7]);
        }
    }

    #pragma unroll
    for (int jj = 0; jj < 4; ++jj) {
        float bv = bias[j0 + tcol4 + jj];
        float2 p01 = unpack2(acc[2 * jj]);
        float2 p23 = unpack2(acc[2 * jj + 1]);
        float4 outv = make_float4(p01.x + bv, p01.y + bv, p23.x + bv, p23.y + bv);
        size_t c = (size_t)bx * 64 + tcol4 + jj;
        *(float4*)&g_xq[(size_t)t * 65536 + c * 64 + trow4] = outv;
    }
}

// ======================= Phase 2: persistent recurrence =====================
// 128 CTAs x 256 thr. CTA owns 2 hidden units (8 gate-cols c = g*2+uu).
// Warp kc consumes h units [kc*32, kc*32+32) — produced by CTA group kc
// (CTAs kc*16..kc*16+15). Each warp independently polls ONE counting flag
// (==16) for its group, broadcast-coalesced + nanosleep backoff. 2 full
// syncs per step; update by warps 0-1 with named bar + red.release.
__global__ __launch_bounds__(NTHR, 1) void lstm_seq_kernel(
    const float* __restrict__ Wf, const float* __restrict__ Wi,
    const float* __restrict__ Wg, const float* __restrict__ Wo,
    float* __restrict__ out)
{
    __shared__ ull wh2[2048];      // [k][8c] dup pairs, 16KB
    __shared__ ull pp[2048];       // [8 kc][8 c][32 bp] partials, 16KB
    __shared__ ull gate_s[256];    // [8 c][32 bp]
    __shared__ ull c_s[64];        // [2 u][32 bp]

    const int tx   = threadIdx.x;
    const int bx   = blockIdx.x;
    const int u0   = bx << 1;
    const int kc   = tx >> 5;      // warp id = k-chunk (32 k each)
    const int lane = tx & 31;      // batch-pair

    // ---- load Wh slice (rows 256..511), duplicated pairs wh2[k*8 + c] ----
    for (int idx = tx; idx < 2048; idx += NTHR) {
        int k = idx >> 3, c = idx & 7;
        const float* W = (c < 4) ? ((c < 2) ? Wf : Wi) : ((c < 6) ? Wg : Wo);
        float w = W[(size_t)(256 + k) * 256 + u0 + (c & 1)];
        wh2[idx] = pack2(w, w);
    }

    // ---- init h(0)=0, c=0 ----
    if (tx < 64) {
        c_s[tx] = 0ull;
        int u = tx >> 5, bp = tx & 31;
        *(ull*)&g_hbuf[0][(u0 + u) * 64 + (bp << 1)] = 0ull;
    }
    __syncthreads();
    if (tx == 0) red_rel(&g_cflag[(bx >> 4) << 5]);

    const int rg = kc >> 1;        // gate of my reduce column (rc = kc)
    const size_t xq_off = (size_t)(rg * 256 + u0 + (kc & 1)) * 64 + (lane << 1);

    float* outs = out;
    float* hxo  = out + (size_t)SEQ * 64 * 256;
    float* cxo  = hxo + 64 * 256;

    const ull* wbase = wh2 + (kc << 8);

    for (int t = 0; t < SEQ; ++t) {
        // prefetch x-projection
        ull xq = *(const ull*)&g_xq[(size_t)t * 65536 + xq_off];

        // per-warp wait: broadcast acquire-load of my group's counter (==16)
        {
            const unsigned* fp = &g_cflag[((t << 3) + kc) << 5];
            unsigned v = ld_acq(fp);
            while (v != 16u) { __nanosleep(40); v = ld_acq(fp); }
        }

        // ---- GEMM: acc[c] += sum over 32 k of h[kc*32+k][2lane..] * w[k][c] ----
        const float* hb = g_hbuf[t & 1] + (kc << 11) + (lane << 1);
        ull acc[8];
        #pragma unroll
        for (int i = 0; i < 8; ++i) acc[i] = 0ull;
        #pragma unroll 8
        for (int k = 0; k < 32; ++k) {
            ull hh = ldcg_u64(hb + (k << 6));
            const ulonglong2* wv = (const ulonglong2*)(wbase + (k << 3));
            ulonglong2 w01 = wv[0], w23 = wv[1], w45 = wv[2], w67 = wv[3];
            acc[0] = fma2(hh, w01.x, acc[0]); acc[1] = fma2(hh, w01.y, acc[1]);
            acc[2] = fma2(hh, w23.x, acc[2]); acc[3] = fma2(hh, w23.y, acc[3]);
            acc[4] = fma2(hh, w45.x, acc[4]); acc[5] = fma2(hh, w45.y, acc[5]);
            acc[6] = fma2(hh, w67.x, acc[6]); acc[7] = fma2(hh, w67.y, acc[7]);
        }
        {
            ull* pdst = pp + (kc << 8) + lane;
            #pragma unroll
            for (int c = 0; c < 8; ++c) pdst[c << 5] = acc[c];
        }
        __syncthreads();                         // #1: pp ready (and h(t) reads done CTA-wide)

        // ---- reduce 8 partials + xq, activation ----
        ull a0 = add2(pp[tx],        pp[tx + 256]);
        ull a1 = add2(pp[tx + 512],  pp[tx + 768]);
        ull a2 = add2(pp[tx + 1024], pp[tx + 1280]);
        ull a3 = add2(pp[tx + 1536], pp[tx + 1792]);
        ull s  = add2(add2(add2(a0, a1), add2(a2, a3)), xq);

        float2 v = unpack2(s);
        float2 a;
        if (rg == 2) { a.x = ftanh(v.x);    a.y = ftanh(v.y); }
        else         { a.x = fsigmoid(v.x); a.y = fsigmoid(v.y); }
        gate_s[tx] = pack2(a.x, a.y);
        __syncthreads();                         // #2: gates ready

        // ---- state update by warps 0-1; release flag BEFORE output stores ----
        if (tx < 64) {
            int u = tx >> 5, bp = tx & 31;
            float2 f  = unpack2(gate_s[tx]);
            float2 ii = unpack2(gate_s[64 + tx]);
            float2 gg = unpack2(gate_s[128 + tx]);
            float2 oo = unpack2(gate_s[192 + tx]);
            float2 co = unpack2(c_s[tx]);
            float c0 = f.x * co.x + ii.x * gg.x;
            float c1 = f.y * co.y + ii.y * gg.y;
            c_s[tx] = pack2(c0, c1);
            float h0 = oo.x * ftanh(c0);
            float h1 = oo.y * ftanh(c1);
            int j = u0 + u;
            int b = bp << 1;
            *(ull*)&g_hbuf[(t + 1) & 1][j * 64 + b] = pack2(h0, h1);
            asm volatile("bar.sync 1, 64;" ::: "memory");   // warps 0-1 only
            if (tx == 0) red_rel(&g_cflag[(((t + 1) << 3) + (bx >> 4)) << 5]);
            outs[((size_t)t * 64 + b) * 256 + j]     = h0;
            outs[((size_t)t * 64 + b + 1) * 256 + j] = h1;
            if (t == SEQ - 1) {
                hxo[b * 256 + j] = h0; hxo[(b + 1) * 256 + j] = h1;
                cxo[b * 256 + j] = c0; cxo[(b + 1) * 256 + j] = c1;
            }
        }
        // no trailing sync: next-step hazards covered by per-warp poll + sync #1/#2
    }
}

// ============================== launch ======================================
extern "C" void kernel_launch(void* const* d_in, const int* in_sizes, int n_in,
                              void* d_out, int out_size)
{
    (void)in_sizes; (void)n_in; (void)out_size;
    const float* X  = (const float*)d_in[0];
    const float* Wf = (const float*)d_in[1];
    const float* bf = (const float*)d_in[2];
    const float* Wi = (const float*)d_in[3];
    const float* bi = (const float*)d_in[4];
    const float* Wg = (const float*)d_in[5];
    const float* bg = (const float*)d_in[6];
    const float* Wo = (const float*)d_in[7];
    const float* bo = (const float*)d_in[8];
    float* out = (float*)d_out;

    dim3 g1(16, 1024);
    xproj_kernel<<<g1, 256>>>(X, Wf, Wi, Wg, Wo, bf, bi, bg, bo);

    lstm_seq_kernel<<<NBLK, NTHR>>>(Wf, Wi, Wg, Wo, out);
}